// round 13
// baseline (speedup 1.0000x reference)
#include <cuda_runtime.h>
#include <math.h>

#define D    1024
#define H    8
#define HD   128
#define T    8193
#define NBLK 148
#define NTHR 1024
#define SCALE 0.08838834764831845f    // 1/sqrt(128)

// ---- scratch (device globals; no allocation allowed) ----
__device__ float g_q0[D];              // Wq@cls + bq
__device__ float g_u[H * D];           // u_h = Wk_h^T q0_h
__device__ float g_wcp[256 * 2 * D];   // Wc@Wo partials: [p][c][j], 256 partials
__device__ float g_G[2 * H * D];       // G[c][h][j]
__device__ float g_bias[2];
__device__ float g_S[H];               // per-head sum of exp
__device__ float g_w[H * D];           // unnormalized weighted token sums
__device__ unsigned int g_barcnt;      // grid barrier counter (self-resetting)
__device__ volatile unsigned int g_sense;   // ends each launch at 0 (even # barriers)

// Sense-reversing grid barrier. Safe: grid (148) <= #SMs -> all blocks resident.
__device__ __forceinline__ void grid_barrier(unsigned int ls) {
    __syncthreads();
    if (threadIdx.x == 0) {
        __threadfence();
        unsigned int old = atomicAdd(&g_barcnt, 1u);
        if (old == gridDim.x - 1) {
            g_barcnt = 0;
            __threadfence();
            g_sense = ls;
        } else {
            while (g_sense != ls) __nanosleep(32);
        }
        __threadfence();
    }
    __syncthreads();
}

union SmemU {
    float us[H * D];                                  // phase C: 32 KB u vectors
    struct { float part[NTHR]; float q0s[HD]; float wcm[2][16]; } ab;
    struct { float red0[NTHR]; float red1[NTHR]; } d; // reductions
};

__global__ void __launch_bounds__(NTHR, 1)
Kfused(const float* __restrict__ x,  const float* __restrict__ cls,
       const float* __restrict__ Wq, const float* __restrict__ bq,
       const float* __restrict__ Wk, const float* __restrict__ Wv,
       const float* __restrict__ bv, const float* __restrict__ Wo,
       const float* __restrict__ bo, const float* __restrict__ Wc,
       const float* __restrict__ bc, float* __restrict__ out) {
    __shared__ SmemU su;
    __shared__ float s_wt[64 * 8];       // exp weights, persists C -> D
    __shared__ float s_rS[H];
    int tid = threadIdx.x, warp = tid >> 5, lane = tid & 31;
    int b = blockIdx.x;

    // ================= Phase A: q0 | Wc@Wo partials | zero scratch ==========
    if (b < 32) {
        // q0: 32 warps x 1 row each -> 1024 rows over 32 blocks
        int row = b * 32 + warp;
        const float4* row4 = reinterpret_cast<const float4*>(Wq) + (size_t)row * (D / 4);
        const float4* c4   = reinterpret_cast<const float4*>(cls);
        float acc = 0.f;
        #pragma unroll
        for (int k = lane; k < D / 4; k += 32) {
            float4 a = row4[k], c = c4[k];
            acc += a.x * c.x + a.y * c.y + a.z * c.z + a.w * c.w;
        }
        #pragma unroll
        for (int o = 16; o; o >>= 1) acc += __shfl_xor_sync(0xffffffffu, acc, o);
        if (lane == 0) g_q0[row] = acc + bq[row];
    } else if (b < 96) {
        // Wc@Wo: 256 partials, each covers 4 Wo rows. p = (b-32)*4 + quarter.
        int p  = (b - 32) * 4 + (tid >> 8);
        int t2 = tid & 255;
        int r0 = p * 4;
        float a0x = 0.f, a0y = 0.f, a0z = 0.f, a0w = 0.f;
        float a1x = 0.f, a1y = 0.f, a1z = 0.f, a1w = 0.f;
        #pragma unroll
        for (int rr = 0; rr < 4; rr++) {
            int r = r0 + rr;
            float4 v = reinterpret_cast<const float4*>(Wo)[(size_t)r * (D / 4) + t2];
            float c0 = __ldg(&Wc[r]), c1 = __ldg(&Wc[D + r]);
            a0x += c0 * v.x; a0y += c0 * v.y; a0z += c0 * v.z; a0w += c0 * v.w;
            a1x += c1 * v.x; a1y += c1 * v.y; a1z += c1 * v.z; a1w += c1 * v.w;
        }
        reinterpret_cast<float4*>(&g_wcp[(p * 2 + 0) * D])[t2] = make_float4(a0x, a0y, a0z, a0w);
        reinterpret_cast<float4*>(&g_wcp[(p * 2 + 1) * D])[t2] = make_float4(a1x, a1y, a1z, a1w);
    } else if (b < 126) {
        int idx = (b - 96) * NTHR + tid;              // [0, 30720)
        if (idx < 2 * H * D)      g_G[idx] = 0.f;
        else if (idx < 3 * H * D) g_w[idx - 2 * H * D] = 0.f;
    } else if (b == 126) {
        if (tid < H) g_S[tid] = 0.f;
    }
    grid_barrier(1);

    // ================= Phase B: u | G | bias ================================
    if (b < 64) {
        // u chunk: head h = b>>3, cols jc*128..+128. thread = (col, d-sixteenth)
        int h = b >> 3, jc = b & 7;
        if (tid < HD) su.ab.q0s[tid] = g_q0[h * HD + tid];
        __syncthreads();
        int c  = tid & 127, dh = tid >> 7;            // dh in [0,8)
        int j  = jc * HD + c;
        float acc = 0.f;
        #pragma unroll
        for (int d = dh * 16; d < dh * 16 + 16; d++)
            acc += su.ab.q0s[d] * Wk[(size_t)(h * HD + d) * D + j];
        su.ab.part[tid] = acc;
        __syncthreads();
        if (tid < 128) {
            float s = 0.f;
            #pragma unroll
            for (int dh2 = 0; dh2 < 8; dh2++) s += su.ab.part[dh2 * 128 + tid];
            g_u[h * D + jc * HD + tid] = s;
        }
    } else if (b < 128) {
        // G: 64 row-groups of 16 Wv rows. bg = b-64. quarter handles 4 rows.
        int bg = b - 64, r0 = bg * 16, h = bg >> 3;
        if (tid < 32) {
            int ch = tid >> 4, rr = tid & 15;
            float s = 0.f;
            #pragma unroll 8
            for (int p = 0; p < 256; p++) s += g_wcp[(p * 2 + ch) * D + r0 + rr];
            su.ab.wcm[ch][rr] = s;
        }
        __syncthreads();
        int t2 = tid & 255, q = tid >> 8;
        float a0x = 0.f, a0y = 0.f, a0z = 0.f, a0w = 0.f;
        float a1x = 0.f, a1y = 0.f, a1z = 0.f, a1w = 0.f;
        #pragma unroll
        for (int rr = 0; rr < 4; rr++) {
            int rl = q * 4 + rr;
            int r = r0 + rl;
            float4 v = reinterpret_cast<const float4*>(Wv)[(size_t)r * (D / 4) + t2];
            float c0 = su.ab.wcm[0][rl], c1 = su.ab.wcm[1][rl];
            a0x += c0 * v.x; a0y += c0 * v.y; a0z += c0 * v.z; a0w += c0 * v.w;
            a1x += c1 * v.x; a1y += c1 * v.y; a1z += c1 * v.z; a1w += c1 * v.w;
        }
        float* d0 = &g_G[(0 * H + h) * D + t2 * 4];
        float* d1 = &g_G[(1 * H + h) * D + t2 * 4];
        atomicAdd(d0 + 0, a0x); atomicAdd(d0 + 1, a0y); atomicAdd(d0 + 2, a0z); atomicAdd(d0 + 3, a0w);
        atomicAdd(d1 + 0, a1x); atomicAdd(d1 + 1, a1y); atomicAdd(d1 + 2, a1z); atomicAdd(d1 + 3, a1w);
    } else if (b == 128) {
        // bias = Wcmod.bv + Wc.bo + bc
        float s0 = 0.f, s1 = 0.f;
        if (tid < 256) {
            float4 m0 = make_float4(0.f, 0.f, 0.f, 0.f);
            float4 m1 = make_float4(0.f, 0.f, 0.f, 0.f);
            #pragma unroll 8
            for (int p = 0; p < 256; p++) {
                float4 v0 = reinterpret_cast<const float4*>(&g_wcp[(p * 2 + 0) * D])[tid];
                float4 v1 = reinterpret_cast<const float4*>(&g_wcp[(p * 2 + 1) * D])[tid];
                m0.x += v0.x; m0.y += v0.y; m0.z += v0.z; m0.w += v0.w;
                m1.x += v1.x; m1.y += v1.y; m1.z += v1.z; m1.w += v1.w;
            }
            float4 bvv = reinterpret_cast<const float4*>(bv)[tid];
            float4 bov = reinterpret_cast<const float4*>(bo)[tid];
            float4 wc0 = reinterpret_cast<const float4*>(Wc)[tid];
            float4 wc1 = reinterpret_cast<const float4*>(Wc)[256 + tid];
            s0 = m0.x * bvv.x + m0.y * bvv.y + m0.z * bvv.z + m0.w * bvv.w
               + wc0.x * bov.x + wc0.y * bov.y + wc0.z * bov.z + wc0.w * bov.w;
            s1 = m1.x * bvv.x + m1.y * bvv.y + m1.z * bvv.z + m1.w * bvv.w
               + wc1.x * bov.x + wc1.y * bov.y + wc1.z * bov.z + wc1.w * bov.w;
        }
        su.d.red0[tid] = s0; su.d.red1[tid] = s1;
        __syncthreads();
        for (int o = 512; o; o >>= 1) {
            if (tid < o) { su.d.red0[tid] += su.d.red0[tid + o]; su.d.red1[tid] += su.d.red1[tid + o]; }
            __syncthreads();
        }
        if (tid == 0) { g_bias[0] = su.d.red0[0] + bc[0]; g_bias[1] = su.d.red1[0] + bc[1]; }
    }
    grid_barrier(0);

    // ================= Phase C: x sweep (blocks 0..128, 64 tokens each) =====
    int base = b * 64;
    if (b < 129) {
        #pragma unroll
        for (int i = 0; i < 8; i++) su.us[tid + i * NTHR] = g_u[tid + i * NTHR];
        __syncthreads();

        // warp owns 2 tokens (32 warps x 2 = 64)
        int tbase = base + warp * 2;
        const float* ptr[2];
        #pragma unroll
        for (int tt = 0; tt < 2; tt++) {
            int s = tbase + tt;
            ptr[tt] = (s <= 0 || s >= T) ? cls : x + (size_t)(s - 1) * D;
        }
        float acc[16];
        #pragma unroll
        for (int i = 0; i < 16; i++) acc[i] = 0.f;
        #pragma unroll 8
        for (int k = 0; k < 32; k++) {
            int j = k * 32 + lane;
            float uv[8];
            #pragma unroll
            for (int h = 0; h < 8; h++) uv[h] = su.us[h * D + j];
            #pragma unroll
            for (int tt = 0; tt < 2; tt++) {
                float xv = ptr[tt][j];
                #pragma unroll
                for (int h = 0; h < 8; h++) acc[tt * 8 + h] += xv * uv[h];
            }
        }
        #pragma unroll
        for (int o = 16; o; o >>= 1) {
            #pragma unroll
            for (int i = 0; i < 16; i++) acc[i] += __shfl_xor_sync(0xffffffffu, acc[i], o);
        }
        if (lane < 16) {
            int tt = lane >> 3, h = lane & 7;        // lane r owns acc[r]
            int s = tbase + tt;
            int slot = (warp * 2 + tt) * 8 + h;
            s_wt[slot] = (s < T) ? expf(acc[lane] * SCALE) : 0.f;
        }
        __syncthreads();

        if (warp < 8) {
            int h = warp;
            float ssum = 0.f;
            #pragma unroll
            for (int t = lane; t < 64; t += 32) ssum += s_wt[t * 8 + h];
            #pragma unroll
            for (int o = 16; o; o >>= 1) ssum += __shfl_xor_sync(0xffffffffu, ssum, o);
            if (lane == 0) atomicAdd(&g_S[h], ssum);
        }

        // weighted token sums: thread owns dim tid
        float a[8];
        #pragma unroll
        for (int h = 0; h < 8; h++) a[h] = 0.f;
        for (int tt = 0; tt < 64; tt++) {
            int s = base + tt;
            if (s >= T) break;
            const float* p = (s == 0) ? cls : x + (size_t)(s - 1) * D;
            float xv = p[tid];
            #pragma unroll
            for (int h = 0; h < 8; h++) a[h] += s_wt[tt * 8 + h] * xv;
        }
        #pragma unroll
        for (int h = 0; h < 8; h++) atomicAdd(&g_w[h * D + tid], a[h]);
    }
    grid_barrier(1);

    // ================= Phase D: A (blocks 0..128) | logits (block 147) ======
    if (tid < H) s_rS[tid] = 1.f / g_S[tid];
    __syncthreads();

    if (b < 129) {
        if (tid < 64) {
            int s = base + tid;
            if (s >= 1 && s < T) {
                float a = 0.f;
                #pragma unroll
                for (int h = 0; h < 8; h++) a += s_wt[tid * 8 + h] * s_rS[h];
                out[6 + s] = a * 0.125f;             // A[s-1]
            }
        }
    } else if (b == 147) {
        float l0 = 0.f, l1 = 0.f;
        if (tid < 256) {
            #pragma unroll
            for (int h = 0; h < 8; h++) {
                float4 w4 = reinterpret_cast<const float4*>(&g_w[h * D])[tid];
                float4 g0 = reinterpret_cast<const float4*>(&g_G[(0 * H + h) * D])[tid];
                float4 g1 = reinterpret_cast<const float4*>(&g_G[(1 * H + h) * D])[tid];
                float r = s_rS[h];
                l0 += r * (g0.x * w4.x + g0.y * w4.y + g0.z * w4.z + g0.w * w4.w);
                l1 += r * (g1.x * w4.x + g1.y * w4.y + g1.z * w4.z + g1.w * w4.w);
            }
        }
        su.d.red0[tid] = l0; su.d.red1[tid] = l1;
        __syncthreads();
        for (int o = 512; o; o >>= 1) {
            if (tid < o) { su.d.red0[tid] += su.d.red0[tid + o]; su.d.red1[tid] += su.d.red1[tid + o]; }
            __syncthreads();
        }
        if (tid == 0) {
            float L0 = su.d.red0[0] + g_bias[0], L1 = su.d.red1[0] + g_bias[1];
            float mx = fmaxf(L0, L1);
            float e0 = expf(L0 - mx), e1 = expf(L1 - mx);
            float inv = 1.f / (e0 + e1);
            float p0 = e0 * inv, p1 = e1 * inv;
            float yhat = (p1 > p0) ? 1.f : 0.f;      // first-max tie-break like jnp.argmax
            out[0] = L0; out[1] = L1;                // top_instance
            out[2] = p0; out[3] = p1;                // Y_prob
            out[4] = yhat;                           // Y_hat
            out[5] = p0; out[6] = p1;                // y_probs
        }
    }
    grid_barrier(0);                                 // even # barriers: sense ends at 0
}

extern "C" void kernel_launch(void* const* d_in, const int* in_sizes, int n_in,
                              void* d_out, int out_size) {
    const float* x   = (const float*)d_in[0];
    const float* cls = (const float*)d_in[1];
    const float* Wq  = (const float*)d_in[2];
    const float* bq  = (const float*)d_in[3];
    const float* Wk  = (const float*)d_in[4];
    // d_in[5] = bk: per-head constant shift of scores -> softmax-invariant, unused
    const float* Wv  = (const float*)d_in[6];
    const float* bv  = (const float*)d_in[7];
    const float* Wo  = (const float*)d_in[8];
    const float* bo  = (const float*)d_in[9];
    const float* Wc  = (const float*)d_in[10];
    const float* bc  = (const float*)d_in[11];
    float* out = (float*)d_out;

    Kfused<<<NBLK, NTHR>>>(x, cls, Wq, bq, Wk, Wv, bv, Wo, bo, Wc, bc, out);
    (void)in_sizes; (void)n_in; (void)out_size;
}

// round 16
// speedup vs baseline: 1.3818x; 1.3818x over previous
#include <cuda_runtime.h>
#include <math.h>
#include <string.h>

#define D    1024
#define H    8
#define HD   128
#define T    8193
#define NBLK 148
#define NTHR 512
#define TPB  56                        // tokens per block in the sweep
#define SCALE 0.08838834764831845f     // 1/sqrt(128)

typedef unsigned long long ull;

// ---- scratch (device globals; no allocation allowed) ----
__device__ __align__(16) float g_q0[D];            // Wq@cls + bq
__device__ __align__(16) float g_u[H * D];         // u_h = Wk_h^T q0_h
__device__ __align__(16) float g_wcp[128 * 2 * D]; // Wc@Wo partials [p][c][j]
__device__ __align__(16) float g_G[2 * H * D];     // G[c][h][j]
__device__ float g_bias[2];
__device__ float g_S[H];                           // per-head sum of exp
__device__ __align__(16) float g_w[H * D];         // unnormalized weighted sums
__device__ unsigned int g_barcnt;
__device__ volatile unsigned int g_sense;          // ends at 0 (even # barriers)

// packed f32x2 fma: d = a*b + d (per 32-bit half)
#define FMA2(d, a, b) asm("fma.rn.f32x2 %0, %1, %2, %0;" : "+l"(d) : "l"(a), "l"(b))

__device__ __forceinline__ float2 u2f(ull v) { float2 f; memcpy(&f, &v, 8); return f; }
__device__ __forceinline__ ull f2u(float2 v) { ull u; memcpy(&u, &v, 8); return u; }

// Sense-reversing grid barrier. Safe: grid (148) <= #SMs -> all blocks resident.
__device__ __forceinline__ void grid_barrier(unsigned int ls) {
    __syncthreads();
    if (threadIdx.x == 0) {
        __threadfence();
        unsigned int old = atomicAdd(&g_barcnt, 1u);
        if (old == gridDim.x - 1) {
            g_barcnt = 0;
            __threadfence();
            g_sense = ls;
        } else {
            while (g_sense != ls) __nanosleep(32);
        }
        __threadfence();
    }
    __syncthreads();
}

union SmemU {
    ull us2[H * 512];                                  // phase C: u as f32 pairs (32 KB)
    struct { float part[NTHR]; float q0s[HD]; float wcm[2][16]; } ab;
    struct { float red0[NTHR]; float red1[NTHR]; } d;  // reductions
};

__global__ void __launch_bounds__(NTHR, 1)
Kfused(const float* __restrict__ x,  const float* __restrict__ cls,
       const float* __restrict__ Wq, const float* __restrict__ bq,
       const float* __restrict__ Wk, const float* __restrict__ Wv,
       const float* __restrict__ bv, const float* __restrict__ Wo,
       const float* __restrict__ bo, const float* __restrict__ Wc,
       const float* __restrict__ bc, float* __restrict__ out) {
    __shared__ SmemU su;
    __shared__ float2 s_wt2[TPB * 8];   // exp weights duplicated (e,e), persists C->D
    __shared__ float s_rS[H];
    int tid = threadIdx.x, warp = tid >> 5, lane = tid & 31;
    int b = blockIdx.x;

    // ================= Phase A: q0 | Wc@Wo partials | zero scratch ==========
    if (b < 64) {
        // q0: 16 warps x 1 row, rows b*16+warp
        int row = b * 16 + warp;
        const float4* row4 = reinterpret_cast<const float4*>(Wq) + (size_t)row * (D / 4);
        const float4* c4   = reinterpret_cast<const float4*>(cls);
        float acc = 0.f;
        #pragma unroll
        for (int k = lane; k < D / 4; k += 32) {
            float4 a = row4[k], c = c4[k];
            acc += a.x * c.x + a.y * c.y + a.z * c.z + a.w * c.w;
        }
        #pragma unroll
        for (int o = 16; o; o >>= 1) acc += __shfl_xor_sync(0xffffffffu, acc, o);
        if (lane == 0) g_q0[row] = acc + bq[row];
    } else if (b < 128) {
        // Wc@Wo: 128 partials of 8 rows each. p = (b-64)*2 + half.
        int p  = (b - 64) * 2 + (tid >> 8);
        int t2 = tid & 255;
        int r0 = p * 8;
        float a0x = 0.f, a0y = 0.f, a0z = 0.f, a0w = 0.f;
        float a1x = 0.f, a1y = 0.f, a1z = 0.f, a1w = 0.f;
        #pragma unroll
        for (int rr = 0; rr < 8; rr++) {
            int r = r0 + rr;
            float4 v = reinterpret_cast<const float4*>(Wo)[(size_t)r * (D / 4) + t2];
            float c0 = __ldg(&Wc[r]), c1 = __ldg(&Wc[D + r]);
            a0x += c0 * v.x; a0y += c0 * v.y; a0z += c0 * v.z; a0w += c0 * v.w;
            a1x += c1 * v.x; a1y += c1 * v.y; a1z += c1 * v.z; a1w += c1 * v.w;
        }
        reinterpret_cast<float4*>(&g_wcp[(p * 2 + 0) * D])[t2] = make_float4(a0x, a0y, a0z, a0w);
        reinterpret_cast<float4*>(&g_wcp[(p * 2 + 1) * D])[t2] = make_float4(a1x, a1y, a1z, a1w);
    } else {
        // zero g_G (16384) + g_w (8192) + g_S (8), grid-stride over 20 blocks
        for (int i = (b - 128) * NTHR + tid; i < 3 * H * D + H; i += 20 * NTHR) {
            if (i < 2 * H * D)          g_G[i] = 0.f;
            else if (i < 3 * H * D)     g_w[i - 2 * H * D] = 0.f;
            else                        g_S[i - 3 * H * D] = 0.f;
        }
    }
    grid_barrier(1);

    // ================= Phase B: u | G | bias ================================
    if (b < 64) {
        // u chunk: head h = b>>3, cols jc*128..+128. thread = (col, d-quarter)
        int h = b >> 3, jc = b & 7;
        if (tid < HD) su.ab.q0s[tid] = g_q0[h * HD + tid];
        __syncthreads();
        int c  = tid & 127, dh = tid >> 7;            // dh in [0,4), 32 d's each
        int j  = jc * HD + c;
        float acc = 0.f;
        #pragma unroll 8
        for (int d = dh * 32; d < dh * 32 + 32; d++)
            acc += su.ab.q0s[d] * Wk[(size_t)(h * HD + d) * D + j];
        su.ab.part[tid] = acc;
        __syncthreads();
        if (tid < 128)
            g_u[h * D + jc * HD + tid] = su.ab.part[tid] + su.ab.part[tid + 128]
                                       + su.ab.part[tid + 256] + su.ab.part[tid + 384];
    } else if (b < 128) {
        // G: 64 row-groups of 16 Wv rows. halves handle 8 rows each.
        int bg = b - 64, r0 = bg * 16, h = bg >> 3;
        if (tid < 32) {
            int ch = tid >> 4, rr = tid & 15;
            float s = 0.f;
            #pragma unroll 8
            for (int p = 0; p < 128; p++) s += g_wcp[(p * 2 + ch) * D + r0 + rr];
            su.ab.wcm[ch][rr] = s;
        }
        __syncthreads();
        int t2 = tid & 255, half = tid >> 8;
        float a0x = 0.f, a0y = 0.f, a0z = 0.f, a0w = 0.f;
        float a1x = 0.f, a1y = 0.f, a1z = 0.f, a1w = 0.f;
        #pragma unroll
        for (int rr = 0; rr < 8; rr++) {
            int rl = half * 8 + rr;
            int r = r0 + rl;
            float4 v = reinterpret_cast<const float4*>(Wv)[(size_t)r * (D / 4) + t2];
            float c0 = su.ab.wcm[0][rl], c1 = su.ab.wcm[1][rl];
            a0x += c0 * v.x; a0y += c0 * v.y; a0z += c0 * v.z; a0w += c0 * v.w;
            a1x += c1 * v.x; a1y += c1 * v.y; a1z += c1 * v.z; a1w += c1 * v.w;
        }
        float* d0 = &g_G[(0 * H + h) * D + t2 * 4];
        float* d1 = &g_G[(1 * H + h) * D + t2 * 4];
        atomicAdd(d0 + 0, a0x); atomicAdd(d0 + 1, a0y); atomicAdd(d0 + 2, a0z); atomicAdd(d0 + 3, a0w);
        atomicAdd(d1 + 0, a1x); atomicAdd(d1 + 1, a1y); atomicAdd(d1 + 2, a1z); atomicAdd(d1 + 3, a1w);
    } else if (b == 128) {
        // bias = Wcmod.bv + Wc.bo + bc
        float s0 = 0.f, s1 = 0.f;
        if (tid < 256) {
            float4 m0 = make_float4(0.f, 0.f, 0.f, 0.f);
            float4 m1 = make_float4(0.f, 0.f, 0.f, 0.f);
            #pragma unroll 8
            for (int p = 0; p < 128; p++) {
                float4 v0 = reinterpret_cast<const float4*>(&g_wcp[(p * 2 + 0) * D])[tid];
                float4 v1 = reinterpret_cast<const float4*>(&g_wcp[(p * 2 + 1) * D])[tid];
                m0.x += v0.x; m0.y += v0.y; m0.z += v0.z; m0.w += v0.w;
                m1.x += v1.x; m1.y += v1.y; m1.z += v1.z; m1.w += v1.w;
            }
            float4 bvv = reinterpret_cast<const float4*>(bv)[tid];
            float4 bov = reinterpret_cast<const float4*>(bo)[tid];
            float4 wc0 = reinterpret_cast<const float4*>(Wc)[tid];
            float4 wc1 = reinterpret_cast<const float4*>(Wc)[256 + tid];
            s0 = m0.x * bvv.x + m0.y * bvv.y + m0.z * bvv.z + m0.w * bvv.w
               + wc0.x * bov.x + wc0.y * bov.y + wc0.z * bov.z + wc0.w * bov.w;
            s1 = m1.x * bvv.x + m1.y * bvv.y + m1.z * bvv.z + m1.w * bvv.w
               + wc1.x * bov.x + wc1.y * bov.y + wc1.z * bov.z + wc1.w * bov.w;
        }
        su.d.red0[tid] = s0; su.d.red1[tid] = s1;
        __syncthreads();
        for (int o = 256; o; o >>= 1) {
            if (tid < o) { su.d.red0[tid] += su.d.red0[tid + o]; su.d.red1[tid] += su.d.red1[tid + o]; }
            __syncthreads();
        }
        if (tid == 0) { g_bias[0] = su.d.red0[0] + bc[0]; g_bias[1] = su.d.red1[0] + bc[1]; }
    }
    grid_barrier(0);

    // ================= Phase C: x sweep, ALL 148 blocks, 56 tokens each =====
    int base = b * TPB;
    {
        const ull* gu2 = reinterpret_cast<const ull*>(g_u);
        for (int i = tid; i < H * 512; i += NTHR) su.us2[i] = gu2[i];
        __syncthreads();

        if (warp < 14) {                        // 14 warps x 4 tokens = 56
            int tbase = base + warp * 4;
            const ull* xp[4];
            #pragma unroll
            for (int tt = 0; tt < 4; tt++) {
                int s = tbase + tt;
                xp[tt] = reinterpret_cast<const ull*>(
                    (s <= 0 || s >= T) ? cls : x + (size_t)(s - 1) * D);
            }
            ull acc[32];
            #pragma unroll
            for (int i = 0; i < 32; i++) acc[i] = 0ull;
            #pragma unroll 4
            for (int k = 0; k < 16; k++) {
                int jp = k * 32 + lane;         // pair index
                ull uv[8];
                #pragma unroll
                for (int h = 0; h < 8; h++) uv[h] = su.us2[h * 512 + jp];
                #pragma unroll
                for (int tt = 0; tt < 4; tt++) {
                    ull xv = xp[tt][jp];
                    #pragma unroll
                    for (int h = 0; h < 8; h++) FMA2(acc[tt * 8 + h], xv, uv[h]);
                }
            }
            float red[32];
            #pragma unroll
            for (int i = 0; i < 32; i++) { float2 f = u2f(acc[i]); red[i] = f.x + f.y; }
            #pragma unroll
            for (int o = 16; o; o >>= 1) {
                #pragma unroll
                for (int i = 0; i < 32; i++) red[i] += __shfl_xor_sync(0xffffffffu, red[i], o);
            }
            // static-index select: lane i takes red[i] (no dynamic reg indexing)
            float v = 0.f;
            #pragma unroll
            for (int i = 0; i < 32; i++) v = (lane == i) ? red[i] : v;
            int tt = lane >> 3, h = lane & 7;
            int s = tbase + tt;
            float e = (s < T) ? expf(v * SCALE) : 0.f;
            s_wt2[(warp * 4 + tt) * 8 + h] = make_float2(e, e);
        }
        __syncthreads();

        // per-head block sum -> atomic S (warps 0..7)
        if (warp < 8) {
            int h = warp;
            float ssum = 0.f;
            for (int t = lane; t < TPB; t += 32) ssum += s_wt2[t * 8 + h].x;
            #pragma unroll
            for (int o = 16; o; o >>= 1) ssum += __shfl_xor_sync(0xffffffffu, ssum, o);
            if (lane == 0) atomicAdd(&g_S[h], ssum);
        }

        // pass 2: thread owns dim pair tid -> f32x2 weighted accumulation
        ull acc2[8];
        #pragma unroll
        for (int h = 0; h < 8; h++) acc2[h] = 0ull;
        for (int tt = 0; tt < TPB; tt++) {
            int s = base + tt;
            if (s >= T) break;
            const float* p = (s == 0) ? cls : x + (size_t)(s - 1) * D;
            ull xv = reinterpret_cast<const ull*>(p)[tid];
            #pragma unroll
            for (int h = 0; h < 8; h++) {
                ull wp = f2u(s_wt2[tt * 8 + h]);   // (e,e) pre-duplicated
                FMA2(acc2[h], xv, wp);
            }
        }
        #pragma unroll
        for (int h = 0; h < 8; h++) {
            float2 f = u2f(acc2[h]);
            atomicAdd(&g_w[h * D + tid * 2 + 0], f.x);
            atomicAdd(&g_w[h * D + tid * 2 + 1], f.y);
        }
    }
    grid_barrier(1);

    // ================= Phase D: A (all blocks) | logits (block 0) ===========
    if (tid < H) s_rS[tid] = 1.f / g_S[tid];
    __syncthreads();

    if (tid < TPB) {
        int s = base + tid;
        if (s >= 1 && s < T) {
            float a = 0.f;
            #pragma unroll
            for (int h = 0; h < 8; h++) a += s_wt2[tid * 8 + h].x * s_rS[h];
            out[6 + s] = a * 0.125f;               // A[s-1]
        }
    }
    if (b == 0) {
        __syncthreads();
        float l0 = 0.f, l1 = 0.f;
        if (tid < 256) {
            #pragma unroll
            for (int h = 0; h < 8; h++) {
                float4 w4 = reinterpret_cast<const float4*>(&g_w[h * D])[tid];
                float4 g0 = reinterpret_cast<const float4*>(&g_G[(0 * H + h) * D])[tid];
                float4 g1 = reinterpret_cast<const float4*>(&g_G[(1 * H + h) * D])[tid];
                float r = s_rS[h];
                l0 += r * (g0.x * w4.x + g0.y * w4.y + g0.z * w4.z + g0.w * w4.w);
                l1 += r * (g1.x * w4.x + g1.y * w4.y + g1.z * w4.z + g1.w * w4.w);
            }
        }
        su.d.red0[tid] = l0; su.d.red1[tid] = l1;
        __syncthreads();
        for (int o = 256; o; o >>= 1) {
            if (tid < o) { su.d.red0[tid] += su.d.red0[tid + o]; su.d.red1[tid] += su.d.red1[tid + o]; }
            __syncthreads();
        }
        if (tid == 0) {
            float L0 = su.d.red0[0] + g_bias[0], L1 = su.d.red1[0] + g_bias[1];
            float mx = fmaxf(L0, L1);
            float e0 = expf(L0 - mx), e1 = expf(L1 - mx);
            float inv = 1.f / (e0 + e1);
            float p0 = e0 * inv, p1 = e1 * inv;
            float yhat = (p1 > p0) ? 1.f : 0.f;    // first-max tie-break like jnp.argmax
            out[0] = L0; out[1] = L1;              // top_instance
            out[2] = p0; out[3] = p1;              // Y_prob
            out[4] = yhat;                         // Y_hat
            out[5] = p0; out[6] = p1;              // y_probs
        }
    }
    grid_barrier(0);                               // even # barriers: sense ends at 0
}

extern "C" void kernel_launch(void* const* d_in, const int* in_sizes, int n_in,
                              void* d_out, int out_size) {
    const float* x   = (const float*)d_in[0];
    const float* cls = (const float*)d_in[1];
    const float* Wq  = (const float*)d_in[2];
    const float* bq  = (const float*)d_in[3];
    const float* Wk  = (const float*)d_in[4];
    // d_in[5] = bk: per-head constant shift of scores -> softmax-invariant, unused
    const float* Wv  = (const float*)d_in[6];
    const float* bv  = (const float*)d_in[7];
    const float* Wo  = (const float*)d_in[8];
    const float* bo  = (const float*)d_in[9];
    const float* Wc  = (const float*)d_in[10];
    const float* bc  = (const float*)d_in[11];
    float* out = (float*)d_out;

    Kfused<<<NBLK, NTHR>>>(x, cls, Wq, bq, Wk, Wv, bv, Wo, bo, Wc, bc, out);
    (void)in_sizes; (void)n_in; (void)out_size;
}

// round 17
// speedup vs baseline: 1.6515x; 1.1952x over previous
#include <cuda_runtime.h>
#include <math.h>
#include <string.h>

#define D    1024
#define H    8
#define HD   128
#define T    8193
#define NBLK 148
#define NTHR 512
#define TPB  60                        // tokens per sweep block (138 blocks)
#define NSWP 138
#define SCALE 0.08838834764831845f     // 1/sqrt(128)

typedef unsigned long long ull;

// ---- scratch (device globals; no allocation allowed) ----
__device__ __align__(16) float g_u[H * D];         // u_h = Wk_h^T q0_h (atomic, zeroed at tail)
__device__ __align__(16) float g_wcp[16 * 2 * D];  // Wc@Wo partials [p][c][j] (plain stores)
__device__ __align__(16) float g_G[2 * H * D];     // G[c][h][j] (plain stores, 1 writer/entry)
__device__ float g_bias[2];
__device__ float g_S[H];                           // per-head expsum (atomic, zeroed at tail)
__device__ __align__(16) float g_w[H * D];         // weighted token sums (atomic, zeroed at tail)
__device__ unsigned int g_cnt2;
__device__ volatile unsigned int g_epoch;          // monotonic across replays

// packed f32x2 fma: d = a*b + d (per 32-bit half)
#define FMA2(d, a, b) asm("fma.rn.f32x2 %0, %1, %2, %0;" : "+l"(d) : "l"(a), "l"(b))

__device__ __forceinline__ float2 u2f(ull v) { float2 f; memcpy(&f, &v, 8); return f; }
__device__ __forceinline__ ull f2u(float2 v) { ull u; memcpy(&u, &v, 8); return u; }

// Epoch grid barrier: works for any barrier count, persists across graph replays.
// Safe: grid (148) <= #SMs -> all blocks resident.
__device__ __forceinline__ void ebar() {
    __syncthreads();
    if (threadIdx.x == 0) {
        unsigned int e = g_epoch;
        __threadfence();
        if (atomicAdd(&g_cnt2, 1u) == gridDim.x - 1) {
            g_cnt2 = 0;
            __threadfence();
            g_epoch = e + 1;
        } else {
            while (g_epoch == e) __nanosleep(32);
        }
        __threadfence();
    }
    __syncthreads();
}

union SmemU {
    ulonglong2 us4[H * 256];                        // ph2 sweep: u as f32x4 (32 KB)
    struct { float q0s[8]; } p1;                    // ph1 q0u
    struct { float wcm[2][HD]; } g;                 // ph2 G block
    struct { float red0[NTHR]; float red1[NTHR]; } d;
};

__global__ void __launch_bounds__(NTHR, 1)
Kfused(const float* __restrict__ x,  const float* __restrict__ cls,
       const float* __restrict__ Wq, const float* __restrict__ bq,
       const float* __restrict__ Wk, const float* __restrict__ Wv,
       const float* __restrict__ bv, const float* __restrict__ Wo,
       const float* __restrict__ bo, const float* __restrict__ Wc,
       const float* __restrict__ bc, float* __restrict__ out) {
    __shared__ SmemU su;
    __shared__ float2 s_wt2[TPB * 8];   // exp weights (e,e), persists sweep -> D
    __shared__ float s_rS[H];
    int tid = threadIdx.x, warp = tid >> 5, lane = tid & 31;
    int b = blockIdx.x;

    // ============ Phase 1: fused q0->u (128 blks) | Wc@Wo partials (16) =====
    if (b < 128) {
        // rows r0..r0+8 of q0, then their contribution to u[h]
        int r0 = b * 8, h = b >> 4;
        if (warp < 8) {
            int row = r0 + warp;
            const float4* row4 = reinterpret_cast<const float4*>(Wq) + (size_t)row * (D / 4);
            const float4* c4   = reinterpret_cast<const float4*>(cls);
            float acc = 0.f;
            #pragma unroll
            for (int k = lane; k < D / 4; k += 32) {
                float4 a = row4[k], c = c4[k];
                acc += a.x * c.x + a.y * c.y + a.z * c.z + a.w * c.w;
            }
            #pragma unroll
            for (int o = 16; o; o >>= 1) acc += __shfl_xor_sync(0xffffffffu, acc, o);
            if (lane == 0) su.p1.q0s[warp] = acc + bq[row];
        }
        __syncthreads();
        float q0r[8];
        #pragma unroll
        for (int r = 0; r < 8; r++) q0r[r] = su.p1.q0s[r];
        // u contribution: thread handles cols tid and tid+512
        float accA = 0.f, accB = 0.f;
        #pragma unroll
        for (int r = 0; r < 8; r++) {
            const float* wkr = Wk + (size_t)(r0 + r) * D;
            accA += q0r[r] * wkr[tid];
            accB += q0r[r] * wkr[tid + 512];
        }
        atomicAdd(&g_u[h * D + tid],       accA);
        atomicAdd(&g_u[h * D + tid + 512], accB);
    } else if (b < 144) {
        // Wc@Wo partial p over 64 Wo rows: wcp[p][c][j]
        int p = b - 128, r0 = p * 64;
        float a0A = 0.f, a1A = 0.f, a0B = 0.f, a1B = 0.f;
        #pragma unroll 8
        for (int rr = 0; rr < 64; rr++) {
            int r = r0 + rr;
            const float* wor = Wo + (size_t)r * D;
            float vA = wor[tid], vB = wor[tid + 512];
            float c0 = __ldg(&Wc[r]), c1 = __ldg(&Wc[D + r]);
            a0A += c0 * vA; a1A += c1 * vA;
            a0B += c0 * vB; a1B += c1 * vB;
        }
        g_wcp[(p * 2 + 0) * D + tid]       = a0A;
        g_wcp[(p * 2 + 0) * D + tid + 512] = a0B;
        g_wcp[(p * 2 + 1) * D + tid]       = a1A;
        g_wcp[(p * 2 + 1) * D + tid + 512] = a1B;
    }
    ebar();

    // ============ Phase 2: x sweep (138 blks) | G (8 blks) | bias (1) =======
    int base = b * TPB;
    if (b < NSWP) {
        const ulonglong2* gu4 = reinterpret_cast<const ulonglong2*>(g_u);
        for (int i = tid; i < H * 256; i += NTHR) su.us4[i] = gu4[i];
        __syncthreads();

        if (warp < 15) {                 // 15 warps x 4 tokens = 60
            int tbase = base + warp * 4;
            const ulonglong2* xp[4];
            #pragma unroll
            for (int tt = 0; tt < 4; tt++) {
                int s = tbase + tt;
                xp[tt] = reinterpret_cast<const ulonglong2*>(
                    (s <= 0 || s >= T) ? cls : x + (size_t)(s - 1) * D);
            }
            ull acc[32];
            #pragma unroll
            for (int i = 0; i < 32; i++) acc[i] = 0ull;
            #pragma unroll 2
            for (int k = 0; k < 8; k++) {
                int jq = k * 32 + lane;  // quad index
                ulonglong2 uv[8];
                #pragma unroll
                for (int h = 0; h < 8; h++) uv[h] = su.us4[h * 256 + jq];
                #pragma unroll
                for (int tt = 0; tt < 4; tt++) {
                    ulonglong2 xv = xp[tt][jq];
                    #pragma unroll
                    for (int h = 0; h < 8; h++) {
                        FMA2(acc[tt * 8 + h], xv.x, uv[h].x);
                        FMA2(acc[tt * 8 + h], xv.y, uv[h].y);
                    }
                }
            }
            float red[32];
            #pragma unroll
            for (int i = 0; i < 32; i++) { float2 f = u2f(acc[i]); red[i] = f.x + f.y; }
            #pragma unroll
            for (int o = 16; o; o >>= 1) {
                #pragma unroll
                for (int i = 0; i < 32; i++) red[i] += __shfl_xor_sync(0xffffffffu, red[i], o);
            }
            float v = 0.f;               // static-index select (no dynamic reg index)
            #pragma unroll
            for (int i = 0; i < 32; i++) v = (lane == i) ? red[i] : v;
            int tt = lane >> 3, h = lane & 7;
            int s = tbase + tt;
            float e = (s < T) ? expf(v * SCALE) : 0.f;
            s_wt2[(warp * 4 + tt) * 8 + h] = make_float2(e, e);
        }
        __syncthreads();

        if (warp < 8) {                  // per-head block sum -> atomic S
            int h = warp;
            float ssum = 0.f;
            for (int t = lane; t < TPB; t += 32) ssum += s_wt2[t * 8 + h].x;
            #pragma unroll
            for (int o = 16; o; o >>= 1) ssum += __shfl_xor_sync(0xffffffffu, ssum, o);
            if (lane == 0) atomicAdd(&g_S[h], ssum);
        }

        // pass 2: thread owns dim-pair tid
        ull acc2[8];
        #pragma unroll
        for (int h = 0; h < 8; h++) acc2[h] = 0ull;
        for (int tt = 0; tt < TPB; tt++) {
            int s = base + tt;
            if (s >= T) break;
            const float* p = (s == 0) ? cls : x + (size_t)(s - 1) * D;
            ull xv = reinterpret_cast<const ull*>(p)[tid];
            #pragma unroll
            for (int h = 0; h < 8; h++) {
                ull wp = f2u(s_wt2[tt * 8 + h]);
                FMA2(acc2[h], xv, wp);
            }
        }
        #pragma unroll
        for (int h = 0; h < 8; h++) {
            float2 f = u2f(acc2[h]);
            atomicAdd(&g_w[h * D + tid * 2 + 0], f.x);
            atomicAdd(&g_w[h * D + tid * 2 + 1], f.y);
        }
    } else if (b < NSWP + 8) {
        // G for head h = b-138: G[c][h][j] = sum_{row in h} Wcmod[c][row]*Wv[row][j]
        int h = b - NSWP, r0 = h * HD;
        if (tid < 256) {
            int c = tid >> 7, rr = tid & 127;
            float s = 0.f;
            #pragma unroll
            for (int p = 0; p < 16; p++) s += g_wcp[(p * 2 + c) * D + r0 + rr];
            su.g.wcm[c][rr] = s;
        }
        __syncthreads();
        float g0A = 0.f, g1A = 0.f, g0B = 0.f, g1B = 0.f;
        #pragma unroll 16
        for (int rr = 0; rr < HD; rr++) {
            const float* wvr = Wv + (size_t)(r0 + rr) * D;
            float vA = wvr[tid], vB = wvr[tid + 512];
            float c0 = su.g.wcm[0][rr], c1 = su.g.wcm[1][rr];
            g0A += c0 * vA; g1A += c1 * vA;
            g0B += c0 * vB; g1B += c1 * vB;
        }
        g_G[(0 * H + h) * D + tid]       = g0A;
        g_G[(0 * H + h) * D + tid + 512] = g0B;
        g_G[(1 * H + h) * D + tid]       = g1A;
        g_G[(1 * H + h) * D + tid + 512] = g1B;
    } else if (b == NSWP + 8) {
        // bias = Wcmod.bv + Wc.bo + bc
        float s0 = 0.f, s1 = 0.f;
        {
            float m0A = 0.f, m1A = 0.f, m0B = 0.f, m1B = 0.f;
            #pragma unroll
            for (int p = 0; p < 16; p++) {
                m0A += g_wcp[(p * 2 + 0) * D + tid];
                m0B += g_wcp[(p * 2 + 0) * D + tid + 512];
                m1A += g_wcp[(p * 2 + 1) * D + tid];
                m1B += g_wcp[(p * 2 + 1) * D + tid + 512];
            }
            float bvA = bv[tid], bvB = bv[tid + 512];
            float boA = bo[tid], boB = bo[tid + 512];
            s0 = m0A * bvA + m0B * bvB + Wc[tid] * boA + Wc[tid + 512] * boB;
            s1 = m1A * bvA + m1B * bvB + Wc[D + tid] * boA + Wc[D + tid + 512] * boB;
        }
        su.d.red0[tid] = s0; su.d.red1[tid] = s1;
        __syncthreads();
        for (int o = 256; o; o >>= 1) {
            if (tid < o) { su.d.red0[tid] += su.d.red0[tid + o]; su.d.red1[tid] += su.d.red1[tid + o]; }
            __syncthreads();
        }
        if (tid == 0) { g_bias[0] = su.d.red0[0] + bc[0]; g_bias[1] = su.d.red1[0] + bc[1]; }
    }
    ebar();

    // ============ Phase 3: A output (sweep blocks) | logits (block 0) =======
    if (tid < H) s_rS[tid] = 1.f / g_S[tid];
    __syncthreads();

    if (b < NSWP && tid < TPB) {
        int s = base + tid;
        if (s >= 1 && s < T) {
            float a = 0.f;
            #pragma unroll
            for (int h = 0; h < 8; h++) a += s_wt2[tid * 8 + h].x * s_rS[h];
            out[6 + s] = a * 0.125f;     // A[s-1]
        }
    }
    if (b == 0) {
        __syncthreads();
        float l0 = 0.f, l1 = 0.f;
        if (tid < 256) {
            #pragma unroll
            for (int h = 0; h < 8; h++) {
                float4 w4 = reinterpret_cast<const float4*>(&g_w[h * D])[tid];
                float4 g0 = reinterpret_cast<const float4*>(&g_G[(0 * H + h) * D])[tid];
                float4 g1 = reinterpret_cast<const float4*>(&g_G[(1 * H + h) * D])[tid];
                float r = s_rS[h];
                l0 += r * (g0.x * w4.x + g0.y * w4.y + g0.z * w4.z + g0.w * w4.w);
                l1 += r * (g1.x * w4.x + g1.y * w4.y + g1.z * w4.z + g1.w * w4.w);
            }
        }
        su.d.red0[tid] = l0; su.d.red1[tid] = l1;
        __syncthreads();
        for (int o = 256; o; o >>= 1) {
            if (tid < o) { su.d.red0[tid] += su.d.red0[tid + o]; su.d.red1[tid] += su.d.red1[tid + o]; }
            __syncthreads();
        }
        if (tid == 0) {
            float L0 = su.d.red0[0] + g_bias[0], L1 = su.d.red1[0] + g_bias[1];
            float mx = fmaxf(L0, L1);
            float e0 = expf(L0 - mx), e1 = expf(L1 - mx);
            float inv = 1.f / (e0 + e1);
            float p0 = e0 * inv, p1 = e1 * inv;
            float yhat = (p1 > p0) ? 1.f : 0.f;  // first-max tie-break like jnp.argmax
            out[0] = L0; out[1] = L1;            // top_instance
            out[2] = p0; out[3] = p1;            // Y_prob
            out[4] = yhat;                       // Y_hat
            out[5] = p0; out[6] = p1;            // y_probs
        }
    }
    ebar();

    // ============ Tail: zero atomic scratch for next replay ================
    // (ordered vs next replay by kernel completion; no barrier needed after)
    {
        int idx = b * NTHR + tid;
        if (idx < H * D)              g_u[idx] = 0.f;
        else if (idx < 2 * H * D)     g_w[idx - H * D] = 0.f;
        else if (idx < 2 * H * D + H) g_S[idx - 2 * H * D] = 0.f;
    }
}

extern "C" void kernel_launch(void* const* d_in, const int* in_sizes, int n_in,
                              void* d_out, int out_size) {
    const float* x   = (const float*)d_in[0];
    const float* cls = (const float*)d_in[1];
    const float* Wq  = (const float*)d_in[2];
    const float* bq  = (const float*)d_in[3];
    const float* Wk  = (const float*)d_in[4];
    // d_in[5] = bk: per-head constant shift of scores -> softmax-invariant, unused
    const float* Wv  = (const float*)d_in[6];
    const float* bv  = (const float*)d_in[7];
    const float* Wo  = (const float*)d_in[8];
    const float* bo  = (const float*)d_in[9];
    const float* Wc  = (const float*)d_in[10];
    const float* bc  = (const float*)d_in[11];
    float* out = (float*)d_out;

    Kfused<<<NBLK, NTHR>>>(x, cls, Wq, bq, Wk, Wv, bv, Wo, bo, Wc, bc, out);
    (void)in_sizes; (void)n_in; (void)out_size;
}